// round 8
// baseline (speedup 1.0000x reference)
#include <cuda_runtime.h>
#include <math.h>

// Problem constants (fixed shapes from reference)
#define HW     3136     // 56*56
#define HW4    784      // HW / 4 (float4 chunks per row)
#define B_SZ   64
#define C_IN   512
#define A_DIM  32
#define C_OUT  512
#define BN_EPS 1e-5f
#define BLOCKS_PER_B 64   // 64 blocks x 8 warps = 512 rows per batch

// Scratch for pooled means: [B, C_in]
__device__ float g_pooled[B_SZ * C_IN];
// Per-batch completion counters. Never reset: finisher = (old+1) % 64 == 0.
__device__ unsigned int g_cnt[B_SZ];

// ---------------------------------------------------------------------------
// Fused kernel: global average pool + per-batch FC chain.
//
// __launch_bounds__(256, 8) caps regs at 32 so the POOL phase keeps
// 8 blocks/SM (full 2048-thread occupancy) — this is the fix for R4's
// regression (40 regs -> 6 blocks/SM -> BW collapse). FC-path spills go to
// local; FC is 64 blocks x ~1us and almost entirely hidden under pool.
//
// Pool: one warp per (b,c) row; 4 independent float4 loads in flight
// (doubles MLP vs 2-wide -> ~24KB in-flight/SM, above the ~14KB
// latency-bandwidth product at 600cyc DRAM latency).
// ---------------------------------------------------------------------------
__global__ __launch_bounds__(256, 8) void fused_kernel(
    const float* __restrict__ x,
    const float* __restrict__ fc_w,         // [A, C_in]
    const float* __restrict__ bn_gamma,     // [A]
    const float* __restrict__ bn_beta,      // [A]
    const float* __restrict__ bn_mean,      // [A]
    const float* __restrict__ bn_var,       // [A]
    const float* __restrict__ channel_fc_w, // [C_in, A]
    const float* __restrict__ channel_fc_b, // [C_in]
    const float* __restrict__ filter_fc_w,  // [C_out, A]
    const float* __restrict__ filter_fc_b,  // [C_out]
    float* __restrict__ out)                // [2 * B * 512]
{
    const int tid  = threadIdx.x;
    const int warp = tid >> 5;
    const int lane = tid & 31;
    const int b    = blockIdx.x >> 6;             // 64 blocks per batch

    // ---------------- pool phase: this warp's row ----------------
    const int gwarp = blockIdx.x * 8 + warp;      // global row = (b, c)
    const float4* __restrict__ row =
        reinterpret_cast<const float4*>(x + (size_t)gwarp * HW);

    // 784 chunks = 6 iterations of 4x32 + 16-chunk remainder (lanes 0-15)
    float s0 = 0.f, s1 = 0.f, s2 = 0.f, s3 = 0.f;
    int i = lane;
    #pragma unroll 3
    for (int it = 0; it < 6; ++it, i += 128) {
        float4 v0 = __ldg(&row[i]);
        float4 v1 = __ldg(&row[i + 32]);
        float4 v2 = __ldg(&row[i + 64]);
        float4 v3 = __ldg(&row[i + 96]);
        s0 += (v0.x + v0.y) + (v0.z + v0.w);
        s1 += (v1.x + v1.y) + (v1.z + v1.w);
        s2 += (v2.x + v2.y) + (v2.z + v2.w);
        s3 += (v3.x + v3.y) + (v3.z + v3.w);
    }
    if (i < HW4) {                                // i = lane + 768
        float4 v0 = __ldg(&row[i]);
        s0 += (v0.x + v0.y) + (v0.z + v0.w);
    }
    float s = (s0 + s1) + (s2 + s3);
    #pragma unroll
    for (int off = 16; off > 0; off >>= 1)
        s += __shfl_xor_sync(0xFFFFFFFFu, s, off);
    if (lane == 0)
        g_pooled[gwarp] = s * (1.0f / (float)HW);

    // ---------------- completion handshake ----------------
    __shared__ int s_last;
    __syncthreads();                 // all 8 rows of this block written
    if (tid == 0) {
        __threadfence();             // publish g_pooled writes
        unsigned int old = atomicAdd(&g_cnt[b], 1u);
        s_last = (((old + 1u) & (BLOCKS_PER_B - 1u)) == 0u);
    }
    __syncthreads();
    if (!s_last) return;

    // ---------------- FC phase (one finisher block per batch) ----------------
    __threadfence();                 // acquire other blocks' g_pooled writes

    // 16B alignment REQUIRED: read via float4 (LDS.128).
    __shared__ __align__(16) float s_pooled[C_IN];
    __shared__ __align__(16) float s_h[A_DIM];

    s_pooled[tid]       = g_pooled[b * C_IN + tid];
    s_pooled[tid + 256] = g_pooled[b * C_IN + tid + 256];
    __syncthreads();

    // h: warp w computes a = w + 8k, k = 0..3 (warp-parallel dots of 512)
    const float4* __restrict__ sp4 = reinterpret_cast<const float4*>(s_pooled);
    #pragma unroll
    for (int k = 0; k < 4; ++k) {
        const int a = warp + k * 8;
        const float4* __restrict__ w4 =
            reinterpret_cast<const float4*>(fc_w + a * C_IN);
        float acc = 0.f;
        #pragma unroll
        for (int j = 0; j < 4; ++j) {
            float4 wv = __ldg(&w4[lane + 32 * j]);
            float4 pv = sp4[lane + 32 * j];
            acc = fmaf(wv.x, pv.x, acc);
            acc = fmaf(wv.y, pv.y, acc);
            acc = fmaf(wv.z, pv.z, acc);
            acc = fmaf(wv.w, pv.w, acc);
        }
        #pragma unroll
        for (int off = 16; off > 0; off >>= 1)
            acc += __shfl_xor_sync(0xFFFFFFFFu, acc, off);
        if (lane == 0) {
            float inv_std = rsqrtf(bn_var[a] + BN_EPS);
            float hv = (acc - bn_mean[a]) * (bn_gamma[a] * inv_std) + bn_beta[a];
            s_h[a] = fmaxf(hv, 0.f);
        }
    }
    __syncthreads();

    // channel + filter attention: thread t handles c = t and c = t+256.
    // Weight tile (128KB total) is L2-hot after the first few finishers;
    // only the last batch's finisher is time-exposed.
    #pragma unroll
    for (int k = 0; k < 2; ++k) {
        const int c = tid + k * 256;
        {
            const float4* __restrict__ w4 =
                reinterpret_cast<const float4*>(channel_fc_w + c * A_DIM);
            float acc = channel_fc_b[c];
            #pragma unroll
            for (int j = 0; j < 8; ++j) {
                float4 wv = __ldg(&w4[j]);
                acc = fmaf(s_h[4 * j + 0], wv.x, acc);
                acc = fmaf(s_h[4 * j + 1], wv.y, acc);
                acc = fmaf(s_h[4 * j + 2], wv.z, acc);
                acc = fmaf(s_h[4 * j + 3], wv.w, acc);
            }
            out[b * C_IN + c] = 1.0f / (1.0f + expf(-acc));
        }
        {
            const float4* __restrict__ w4 =
                reinterpret_cast<const float4*>(filter_fc_w + c * A_DIM);
            float acc = filter_fc_b[c];
            #pragma unroll
            for (int j = 0; j < 8; ++j) {
                float4 wv = __ldg(&w4[j]);
                acc = fmaf(s_h[4 * j + 0], wv.x, acc);
                acc = fmaf(s_h[4 * j + 1], wv.y, acc);
                acc = fmaf(s_h[4 * j + 2], wv.z, acc);
                acc = fmaf(s_h[4 * j + 3], wv.w, acc);
            }
            out[(size_t)B_SZ * C_IN + b * C_OUT + c] = 1.0f / (1.0f + expf(-acc));
        }
    }
}

extern "C" void kernel_launch(void* const* d_in, const int* in_sizes, int n_in,
                              void* d_out, int out_size) {
    const float* x            = (const float*)d_in[0];
    const float* fc_w         = (const float*)d_in[1];
    const float* bn_gamma     = (const float*)d_in[2];
    const float* bn_beta      = (const float*)d_in[3];
    const float* bn_mean      = (const float*)d_in[4];
    const float* bn_var       = (const float*)d_in[5];
    const float* channel_fc_w = (const float*)d_in[6];
    const float* channel_fc_b = (const float*)d_in[7];
    const float* filter_fc_w  = (const float*)d_in[8];
    const float* filter_fc_b  = (const float*)d_in[9];
    float* out = (float*)d_out;

    fused_kernel<<<B_SZ * BLOCKS_PER_B, 256>>>(
        x, fc_w, bn_gamma, bn_beta, bn_mean, bn_var,
        channel_fc_w, channel_fc_b, filter_fc_w, filter_fc_b, out);
}

// round 9
// speedup vs baseline: 1.2439x; 1.2439x over previous
#include <cuda_runtime.h>
#include <math.h>

// Problem constants (fixed shapes from reference)
#define HW     3136     // 56*56
#define HW4    784      // HW / 4 (float4 chunks per row)
#define B_SZ   64
#define C_IN   512
#define A_DIM  32
#define C_OUT  512
#define BN_EPS 1e-5f

// fc kernel dynamic smem layout (floats):
//   s_wT     : [32][513] transposed attention-weight tile
//   s_pooled : [512]
//   s_h      : [32]
#define SWT_STRIDE 513
#define SMEM_FLOATS (A_DIM * SWT_STRIDE + C_IN + A_DIM)

// Scratch for pooled means: [B, C_in]
__device__ float g_pooled[B_SZ * C_IN];

// ---------------------------------------------------------------------------
// Kernel 1: global average pool. One warp per (b, c) row; 4 independent
// float4 loads in flight (vs 2 before) for higher MLP. Calls the PDL
// trigger at block entry so fc_kernel's blocks can launch during the pool's
// final (partially-empty) wave and run their weight-prefetch preamble
// concurrently with the remaining streaming.
// ---------------------------------------------------------------------------
__global__ __launch_bounds__(256) void pool_kernel(const float* __restrict__ x) {
    // PDL: fire as soon as every block has STARTED (not finished). The
    // dependent kernel still gates its g_pooled reads on
    // cudaGridDependencySynchronize(), so correctness is unaffected.
    cudaTriggerProgrammaticLaunchCompletion();

    const int gwarp = (blockIdx.x * blockDim.x + threadIdx.x) >> 5;
    const int lane  = threadIdx.x & 31;
    if (gwarp >= B_SZ * C_IN) return;

    const float4* __restrict__ row =
        reinterpret_cast<const float4*>(x + (size_t)gwarp * HW);

    // 784 chunks = 6 iterations of 4x32 + 16-chunk remainder (lanes 0-15)
    float s0 = 0.f, s1 = 0.f, s2 = 0.f, s3 = 0.f;
    int i = lane;
    #pragma unroll 3
    for (int it = 0; it < 6; ++it, i += 128) {
        float4 v0 = __ldg(&row[i]);
        float4 v1 = __ldg(&row[i + 32]);
        float4 v2 = __ldg(&row[i + 64]);
        float4 v3 = __ldg(&row[i + 96]);
        s0 += (v0.x + v0.y) + (v0.z + v0.w);
        s1 += (v1.x + v1.y) + (v1.z + v1.w);
        s2 += (v2.x + v2.y) + (v2.z + v2.w);
        s3 += (v3.x + v3.y) + (v3.z + v3.w);
    }
    if (i < HW4) {                                // i = lane + 768
        float4 v0 = __ldg(&row[i]);
        s0 += (v0.x + v0.y) + (v0.z + v0.w);
    }
    float s = (s0 + s1) + (s2 + s3);

    #pragma unroll
    for (int off = 16; off > 0; off >>= 1)
        s += __shfl_xor_sync(0xFFFFFFFFu, s, off);

    if (lane == 0)
        g_pooled[gwarp] = s * (1.0f / (float)HW);
}

// ---------------------------------------------------------------------------
// Kernel 2: FC chain (R7 structure — best measured). Grid = 128 blocks:
// block (b, t), t=0 channel / t=1 filter. 512 threads, one output each.
// Weight tile staged into smem transposed via coalesced float4 loads;
// everything before cudaGridDependencySynchronize() overlaps pool's tail.
// ---------------------------------------------------------------------------
__global__ __launch_bounds__(512) void fc_kernel(
    const float* __restrict__ fc_w,         // [A, C_in]
    const float* __restrict__ bn_gamma,     // [A]
    const float* __restrict__ bn_beta,      // [A]
    const float* __restrict__ bn_mean,      // [A]
    const float* __restrict__ bn_var,       // [A]
    const float* __restrict__ channel_fc_w, // [C_in, A]
    const float* __restrict__ channel_fc_b, // [C_in]
    const float* __restrict__ filter_fc_w,  // [C_out, A]
    const float* __restrict__ filter_fc_b,  // [C_out]
    float* __restrict__ out)                // [2 * B * 512]
{
    extern __shared__ __align__(16) float smem[];
    float* s_wT     = smem;                          // [32][513]
    float* s_pooled = smem + A_DIM * SWT_STRIDE;     // [512]
    float* s_h      = s_pooled + C_IN;               // [32]

    const int b    = blockIdx.x >> 1;
    const int t    = blockIdx.x & 1;        // 0 = channel, 1 = filter
    const int tid  = threadIdx.x;
    const int warp = tid >> 5;
    const int lane = tid & 31;

    // ======== PREAMBLE (overlaps pool's tail wave via PDL trigger) ========
    const float* __restrict__ w_mat  = t ? filter_fc_w : channel_fc_w;
    const float* __restrict__ w_bias = t ? filter_fc_b : channel_fc_b;
    const float4* __restrict__ g4 = reinterpret_cast<const float4*>(w_mat);
    #pragma unroll
    for (int k = 0; k < 8; ++k) {
        const int i = tid + k * 512;         // float4 index, lanes contiguous
        float4 v = __ldg(&g4[i]);
        const int f = i << 2;                // first float index
        const int c = f >> 5;                // output row (0..511)
        const int a = f & 31;                // a-offset (multiple of 4)
        s_wT[(a + 0) * SWT_STRIDE + c] = v.x;
        s_wT[(a + 1) * SWT_STRIDE + c] = v.y;
        s_wT[(a + 2) * SWT_STRIDE + c] = v.z;
        s_wT[(a + 3) * SWT_STRIDE + c] = v.w;
    }
    float bias = __ldg(&w_bias[tid]);

    // fc_w rows for this warp's two h-dots (coalesced, 4 lines per LDG)
    const int a0 = warp, a1 = warp + 16;
    const float4* __restrict__ f0 =
        reinterpret_cast<const float4*>(fc_w + a0 * C_IN);
    const float4* __restrict__ f1 =
        reinterpret_cast<const float4*>(fc_w + a1 * C_IN);
    float4 fw00 = __ldg(&f0[lane]);      float4 fw01 = __ldg(&f0[lane + 32]);
    float4 fw02 = __ldg(&f0[lane + 64]); float4 fw03 = __ldg(&f0[lane + 96]);
    float4 fw10 = __ldg(&f1[lane]);      float4 fw11 = __ldg(&f1[lane + 32]);
    float4 fw12 = __ldg(&f1[lane + 64]); float4 fw13 = __ldg(&f1[lane + 96]);

    float bnv0 = __ldg(&bn_var[a0]),   bnv1 = __ldg(&bn_var[a1]);
    float bnm0 = __ldg(&bn_mean[a0]),  bnm1 = __ldg(&bn_mean[a1]);
    float bng0 = __ldg(&bn_gamma[a0]), bng1 = __ldg(&bn_gamma[a1]);
    float bnb0 = __ldg(&bn_beta[a0]),  bnb1 = __ldg(&bn_beta[a1]);

    // ======== wait for pool_kernel results (programmatic edge) ========
    cudaGridDependencySynchronize();

    s_pooled[tid] = g_pooled[b * C_IN + tid];
    __syncthreads();

    // ---- h: warp-parallel dots with pre-loaded fc_w ----
    const float4* __restrict__ sp4 = reinterpret_cast<const float4*>(s_pooled);
    float4 pv0 = sp4[lane];      float4 pv1 = sp4[lane + 32];
    float4 pv2 = sp4[lane + 64]; float4 pv3 = sp4[lane + 96];

    float acc0 = 0.f, acc1 = 0.f;
    acc0 = fmaf(fw00.x, pv0.x, acc0); acc0 = fmaf(fw00.y, pv0.y, acc0);
    acc0 = fmaf(fw00.z, pv0.z, acc0); acc0 = fmaf(fw00.w, pv0.w, acc0);
    acc0 = fmaf(fw01.x, pv1.x, acc0); acc0 = fmaf(fw01.y, pv1.y, acc0);
    acc0 = fmaf(fw01.z, pv1.z, acc0); acc0 = fmaf(fw01.w, pv1.w, acc0);
    acc0 = fmaf(fw02.x, pv2.x, acc0); acc0 = fmaf(fw02.y, pv2.y, acc0);
    acc0 = fmaf(fw02.z, pv2.z, acc0); acc0 = fmaf(fw02.w, pv2.w, acc0);
    acc0 = fmaf(fw03.x, pv3.x, acc0); acc0 = fmaf(fw03.y, pv3.y, acc0);
    acc0 = fmaf(fw03.z, pv3.z, acc0); acc0 = fmaf(fw03.w, pv3.w, acc0);

    acc1 = fmaf(fw10.x, pv0.x, acc1); acc1 = fmaf(fw10.y, pv0.y, acc1);
    acc1 = fmaf(fw10.z, pv0.z, acc1); acc1 = fmaf(fw10.w, pv0.w, acc1);
    acc1 = fmaf(fw11.x, pv1.x, acc1); acc1 = fmaf(fw11.y, pv1.y, acc1);
    acc1 = fmaf(fw11.z, pv1.z, acc1); acc1 = fmaf(fw11.w, pv1.w, acc1);
    acc1 = fmaf(fw12.x, pv2.x, acc1); acc1 = fmaf(fw12.y, pv2.y, acc1);
    acc1 = fmaf(fw12.z, pv2.z, acc1); acc1 = fmaf(fw12.w, pv2.w, acc1);
    acc1 = fmaf(fw13.x, pv3.x, acc1); acc1 = fmaf(fw13.y, pv3.y, acc1);
    acc1 = fmaf(fw13.z, pv3.z, acc1); acc1 = fmaf(fw13.w, pv3.w, acc1);

    #pragma unroll
    for (int off = 16; off > 0; off >>= 1) {
        acc0 += __shfl_xor_sync(0xFFFFFFFFu, acc0, off);
        acc1 += __shfl_xor_sync(0xFFFFFFFFu, acc1, off);
    }
    if (lane == 0) {
        float h0 = (acc0 - bnm0) * (bng0 * rsqrtf(bnv0 + BN_EPS)) + bnb0;
        float h1 = (acc1 - bnm1) * (bng1 * rsqrtf(bnv1 + BN_EPS)) + bnb1;
        s_h[a0] = fmaxf(h0, 0.f);
        s_h[a1] = fmaxf(h1, 0.f);
    }
    __syncthreads();

    // ---- attention output: dot over smem-transposed weights ----
    float acc = bias;
    #pragma unroll
    for (int a = 0; a < A_DIM; ++a)
        acc = fmaf(s_h[a], s_wT[a * SWT_STRIDE + tid], acc);

    out[(size_t)t * (B_SZ * C_IN) + b * C_IN + tid] =
        1.0f / (1.0f + expf(-acc));
}

extern "C" void kernel_launch(void* const* d_in, const int* in_sizes, int n_in,
                              void* d_out, int out_size) {
    const float* x            = (const float*)d_in[0];
    const float* fc_w         = (const float*)d_in[1];
    const float* bn_gamma     = (const float*)d_in[2];
    const float* bn_beta      = (const float*)d_in[3];
    const float* bn_mean      = (const float*)d_in[4];
    const float* bn_var       = (const float*)d_in[5];
    const float* channel_fc_w = (const float*)d_in[6];
    const float* channel_fc_b = (const float*)d_in[7];
    const float* filter_fc_w  = (const float*)d_in[8];
    const float* filter_fc_b  = (const float*)d_in[9];
    float* out = (float*)d_out;

    const int smem_bytes = SMEM_FLOATS * (int)sizeof(float);
    static bool attr_set = false;   // host-side only; idempotent runtime attr
    if (!attr_set) {
        cudaFuncSetAttribute(fc_kernel,
                             cudaFuncAttributeMaxDynamicSharedMemorySize,
                             smem_bytes);
        attr_set = true;
    }

    pool_kernel<<<(B_SZ * C_IN) / 8, 256>>>(x);

    // PDL launch: with pool_kernel's explicit trigger, fc blocks launch
    // during pool's final wave and overlap their weight prefetch with the
    // remaining streaming traffic.
    cudaLaunchConfig_t cfg = {};
    cfg.gridDim  = dim3(B_SZ * 2);
    cfg.blockDim = dim3(512);
    cfg.dynamicSmemBytes = smem_bytes;
    cfg.stream = 0;
    cudaLaunchAttribute attr[1];
    attr[0].id = cudaLaunchAttributeProgrammaticStreamSerialization;
    attr[0].val.programmaticStreamSerializationAllowed = 1;
    cfg.attrs = attr;
    cfg.numAttrs = 1;
    cudaLaunchKernelEx(&cfg, fc_kernel,
                       fc_w, bn_gamma, bn_beta, bn_mean, bn_var,
                       channel_fc_w, channel_fc_b,
                       filter_fc_w, filter_fc_b, out);
}